// round 10
// baseline (speedup 1.0000x reference)
#include <cuda_runtime.h>
#include <math.h>
#include <cstdint>

#define HH 1024
#define WW 1024
#define CC 128
#define NW 16                 // warps per block = columns per block (incl. 2 halo)
#define TPB (NW * 32)
#define COUT (NW - 2)         // 14 output columns per block
#define ROWG 128              // rows per block
#define BATCH 32              // rows per deferred dot-reduce burst

#define VS_FLOATS (2 * 2 * NW * CC)        // 8192  (parity, rowpair, warp, ch)
#define DP_FLOATS (NW * BATCH * 33)        // 16896 (warp, rowslot, lane+pad)
#define SMEM_FLOATS (VS_FLOATS + DP_FLOATS)

// ---- packed f32x2 primitives (sm_103a; PTX-only, ptxas won't auto-fuse) ----
__device__ __forceinline__ uint64_t f2mul(uint64_t a, uint64_t b) {
    uint64_t r; asm("mul.rn.f32x2 %0,%1,%2;" : "=l"(r) : "l"(a), "l"(b)); return r;
}
__device__ __forceinline__ uint64_t f2add(uint64_t a, uint64_t b) {
    uint64_t r; asm("add.rn.f32x2 %0,%1,%2;" : "=l"(r) : "l"(a), "l"(b)); return r;
}
__device__ __forceinline__ uint64_t f2fma(uint64_t a, uint64_t b, uint64_t c) {
    uint64_t r; asm("fma.rn.f32x2 %0,%1,%2,%3;" : "=l"(r) : "l"(a), "l"(b), "l"(c)); return r;
}
__device__ __forceinline__ uint64_t pack2(float x, float y) {
    uint64_t r; asm("mov.b64 %0,{%1,%2};" : "=l"(r) : "f"(x), "f"(y)); return r;
}
__device__ __forceinline__ float hsum2(uint64_t v) {
    float x, y; asm("mov.b64 {%0,%1},%2;" : "=f"(x), "=f"(y) : "l"(v)); return x + y;
}
__device__ __forceinline__ float dot4p(ulonglong2 v) {
    return hsum2(f2fma(v.y, v.y, f2mul(v.x, v.x)));
}

// reduce TWO independent values across the warp in one shared butterfly (6 SHFL)
__device__ __forceinline__ float2 redux2(float a, float b, int lane) {
    const unsigned full = 0xffffffffu;
    float z = (lane < 16) ? a : b;
    float w = (lane < 16) ? b : a;
    w = __shfl_xor_sync(full, w, 16);
    z += w;
    #pragma unroll
    for (int o = 8; o > 0; o >>= 1)
        z += __shfl_xor_sync(full, z, o);
    float t = __shfl_xor_sync(full, z, 16);
    float sa = (lane < 16) ? z : t;
    float sb = (lane < 16) ? t : z;
    return make_float2(sa, sb);
}

__global__ void __launch_bounds__(TPB, 2)
cos_sim_stream(const float* __restrict__ in, float* __restrict__ out)
{
    extern __shared__ float smem[];
    float* vsb = smem;                 // vertical-sum exchange ring
    float* dp  = smem + VS_FLOATS;     // per-warp deferred dot partials

    const int lane = threadIdx.x & 31;
    const int wid  = threadIdx.x >> 5;
    const int col  = blockIdx.x * COUT + wid - 1;     // wid 0 / NW-1 = halo
    const bool colok = ((unsigned)col < (unsigned)WW);
    const bool inner = (wid >= 1) && (wid <= COUT);
    const bool outok = colok && inner;
    const int r0 = blockIdx.y * ROWG;

    float* dprow = dp + wid * (BATCH * 33);

    const float* gcol = in + (size_t)col * CC + lane * 4;
    const size_t rowstep = (size_t)WW * CC;
    auto ld = [&](int h) -> ulonglong2 {
        ulonglong2 v; v.x = 0ull; v.y = 0ull;
        if (colok && (unsigned)h < (unsigned)HH)
            v = *reinterpret_cast<const ulonglong2*>(gcol + (size_t)h * rowstep);
        return v;
    };
    auto scalev = [&](ulonglong2 v, float inv) -> ulonglong2 {
        const uint64_t ip = pack2(inv, inv);
        ulonglong2 r; r.x = f2mul(v.x, ip); r.y = f2mul(v.y, ip); return r;
    };

    // ---- preamble: xn for rows r0-1 .. r0+2; raw rows r0+3..r0+6 staged ----
    ulonglong2 xnA, xnB, xnC, xnD;
    {
        ulonglong2 ra = ld(r0 - 1), rb = ld(r0);
        ulonglong2 rc = ld(r0 + 1), rd = ld(r0 + 2);
        float2 s01 = redux2(dot4p(ra), dot4p(rb), lane);
        float2 s23 = redux2(dot4p(rc), dot4p(rd), lane);
        xnA = scalev(ra, (s01.x >= 1e-16f) ? rsqrtf(s01.x) : 1e8f);
        xnB = scalev(rb, (s01.y >= 1e-16f) ? rsqrtf(s01.y) : 1e8f);
        xnC = scalev(rc, (s23.x >= 1e-16f) ? rsqrtf(s23.x) : 1e8f);
        xnD = scalev(rd, (s23.y >= 1e-16f) ? rsqrtf(s23.y) : 1e8f);
    }
    ulonglong2 stg[2][2];
    stg[0][0] = ld(r0 + 3);  stg[0][1] = ld(r0 + 4);
    stg[1][0] = ld(r0 + 5);  stg[1][1] = ld(r0 + 6);

    #pragma unroll 2
    for (int k = 0; k < ROWG / 2; k++) {
        const int i = 2 * k;
        const int h = r0 + i;
        const int p = k & 1;

        // normalize rows h+3,h+4 NOW (consumed NEXT iteration): this long
        // shuffle/rsqrt chain overlaps the exchange/dot work below.
        ulonglong2 s0 = stg[p][0], s1 = stg[p][1];
        float2 ss = redux2(dot4p(s0), dot4p(s1), lane);
        const ulonglong2 xnE = scalev(s0, (ss.x >= 1e-16f) ? rsqrtf(ss.x) : 1e8f);
        const ulonglong2 xnF = scalev(s1, (ss.y >= 1e-16f) ? rsqrtf(ss.y) : 1e8f);
        stg[p][0] = ld(h + 7);                 // refill, consumed at k+2
        stg[p][1] = ld(h + 8);

        // vertical 3-sums for rows h, h+1 (all inputs normalized last iter)
        ulonglong2 v0, v1;
        v0.x = f2add(f2add(xnA.x, xnB.x), xnC.x);
        v0.y = f2add(f2add(xnA.y, xnB.y), xnC.y);
        v1.x = f2add(f2add(xnB.x, xnC.x), xnD.x);
        v1.y = f2add(f2add(xnB.y, xnC.y), xnD.y);

        // exchange via double-buffered smem (addresses inline, no pointer arrays)
        float* base0 = vsb + ((p * 2 + 0) * NW + wid) * CC + lane * 4;
        float* base1 = base0 + NW * CC;
        *reinterpret_cast<ulonglong2*>(base0) = v0;
        *reinterpret_cast<ulonglong2*>(base1) = v1;
        __syncthreads();                       // one barrier per 2 rows

        if (inner) {                           // warp-uniform
            const ulonglong2 l0 = *reinterpret_cast<const ulonglong2*>(base0 - CC);
            const ulonglong2 q0 = *reinterpret_cast<const ulonglong2*>(base0 + CC);
            const ulonglong2 l1 = *reinterpret_cast<const ulonglong2*>(base1 - CC);
            const ulonglong2 q1 = *reinterpret_cast<const ulonglong2*>(base1 + CC);

            uint64_t t0 = f2mul(xnB.x, f2add(f2add(l0.x, v0.x), q0.x));
            t0 = f2fma(xnB.y, f2add(f2add(l0.y, v0.y), q0.y), t0);
            uint64_t t1 = f2mul(xnC.x, f2add(f2add(l1.x, v1.x), q1.x));
            t1 = f2fma(xnC.y, f2add(f2add(l1.y, v1.y), q1.y), t1);

            dprow[(i & 31) * 33 + lane]       = hsum2(t0);   // defer lane-reduce
            dprow[((i + 1) & 31) * 33 + lane] = hsum2(t1);

            if ((i & 31) == 30) {              // batch of 32 rows complete
                __syncwarp();
                if (outok) {
                    float s = 0.f;
                    #pragma unroll
                    for (int j = 0; j < 32; j++) s += dprow[lane * 33 + j];
                    out[(size_t)(h - 30 + lane) * WW + col] = s - 1.0f;
                }
                __syncwarp();
            }
        }
        xnA = xnC;  xnB = xnD;  xnC = xnE;  xnD = xnF;
    }
}

extern "C" void kernel_launch(void* const* d_in, const int* in_sizes, int n_in,
                              void* d_out, int out_size)
{
    const float* in = (const float*)d_in[0];
    float* out = (float*)d_out;

    const size_t smem_bytes = SMEM_FLOATS * sizeof(float);   // ~98 KB
    cudaFuncSetAttribute(cos_sim_stream,
                         cudaFuncAttributeMaxDynamicSharedMemorySize,
                         (int)smem_bytes);

    dim3 grid((WW + COUT - 1) / COUT, HH / ROWG);   // 74 x 8
    cos_sim_stream<<<grid, TPB, smem_bytes>>>(in, out);
}